// round 2
// baseline (speedup 1.0000x reference)
#include <cuda_runtime.h>
#include <math.h>

// ---------------- problem constants ----------------
#define D_MODEL 512
#define D_FF    2048
#define NHEAD   8
#define DK      64
#define NLAYER  4
#define VOCAB   512
#define BATCH   16
#define LFULL   513
#define LT      512          // target length (L-1)
#define SRC_S   256
#define MT      (BATCH*LT)   // 8192 token rows
#define MS      (BATCH*SRC_S)// 4096 src rows

// ---------------- device scratch (static, no allocation) ----------------
__device__ float g_x  [MT*D_MODEL];
__device__ float g_h  [MT*D_MODEL];
__device__ float g_q  [MT*D_MODEL];
__device__ float g_k  [MT*D_MODEL];   // also holds cross-K (first MS rows)
__device__ float g_v  [MT*D_MODEL];   // also holds cross-V (first MS rows)
__device__ float g_att[MT*D_MODEL];
__device__ float g_sc [BATCH*NHEAD*LT*LT];  // 134 MB score scratch
__device__ float g_ffn[MT*D_FF];
__device__ float g_pe [LT*D_MODEL];
__device__ float g_lg [MT*VOCAB];

// ---------------- positional encoding (fp64 to match numpy) ----------------
__global__ void pe_kernel() {
    int i = blockIdx.x * blockDim.x + threadIdx.x;
    if (i >= LT * D_MODEL) return;
    int t = i / D_MODEL, d = i % D_MODEL;
    int e = d & ~1;
    double div = exp(-(double)e * (log(10000.0) / (double)D_MODEL));
    double ang = (double)t * div;
    g_pe[i] = (float)((d & 1) ? cos(ang) : sin(ang));
}

// ---------------- embedding + PE ----------------
__global__ void embed_kernel(const int* __restrict__ ids, const float* __restrict__ emb) {
    int i = blockIdx.x * blockDim.x + threadIdx.x;
    if (i >= MT * D_MODEL) return;
    int row = i / D_MODEL, d = i % D_MODEL;
    int b = row / LT, t = row % LT;
    int tok = ids[b * LFULL + t];
    g_x[i] = emb[tok * D_MODEL + d] * 22.62741699796952f + g_pe[t * D_MODEL + d];
}

// ---------------- layernorm (ddof=1, denom = std + eps) ----------------
__global__ void ln_kernel(const float* __restrict__ x, float* __restrict__ y,
                          const float* __restrict__ ga, const float* __restrict__ gb) {
    int row = blockIdx.x;
    const float* xr = x + (size_t)row * D_MODEL;
    float*       yr = y + (size_t)row * D_MODEL;
    int t = threadIdx.x;  // 128 threads
    float v[4], s = 0.f, s2 = 0.f;
#pragma unroll
    for (int j = 0; j < 4; j++) {
        v[j] = xr[t + j * 128];
        s += v[j]; s2 += v[j] * v[j];
    }
    __shared__ float red[2][4];
#pragma unroll
    for (int o = 16; o > 0; o >>= 1) {
        s  += __shfl_down_sync(0xffffffffu, s,  o);
        s2 += __shfl_down_sync(0xffffffffu, s2, o);
    }
    if ((t & 31) == 0) { red[0][t >> 5] = s; red[1][t >> 5] = s2; }
    __syncthreads();
    if (t == 0) {
        float S1 = red[0][0] + red[0][1] + red[0][2] + red[0][3];
        float S2 = red[1][0] + red[1][1] + red[1][2] + red[1][3];
        float mean = S1 / 512.0f;
        float var  = fmaxf(0.f, S2 - 512.0f * mean * mean) / 511.0f;
        red[0][0] = mean;
        red[1][0] = 1.0f / (sqrtf(var) + 1e-6f);
    }
    __syncthreads();
    float mean = red[0][0], inv = red[1][0];
#pragma unroll
    for (int j = 0; j < 4; j++) {
        int c = t + j * 128;
        yr[c] = ga[c] * (v[j] - mean) * inv + gb[c];
    }
}

// ---------------- generic GEMM: C = A(MxK) @ W(KxN) + bias [+res] [relu] ----------------
// 64x64 tile, BK=16, 256 threads, 4x4 micro-tile. M%64==0, N%64==0, K%16==0.
__global__ void gemm_kernel(const float* __restrict__ A, const float* __restrict__ W,
                            const float* __restrict__ bias, const float* __restrict__ res,
                            float* __restrict__ C, int M, int N, int K, int relu) {
    __shared__ float As[16][64];
    __shared__ float Bs[16][64];
    int row0 = blockIdx.y * 64, col0 = blockIdx.x * 64;
    int tid = threadIdx.x;
    int tx = tid & 15, ty = tid >> 4;
    int am = tid >> 2, ak = (tid & 3) * 4;
    int bk = tid >> 4, bn = (tid & 15) * 4;
    float acc[4][4] = {};
    for (int k0 = 0; k0 < K; k0 += 16) {
        float4 a4 = *(const float4*)(A + (size_t)(row0 + am) * K + k0 + ak);
        float4 b4 = *(const float4*)(W + (size_t)(k0 + bk) * N + col0 + bn);
        As[ak + 0][am] = a4.x; As[ak + 1][am] = a4.y;
        As[ak + 2][am] = a4.z; As[ak + 3][am] = a4.w;
        *(float4*)&Bs[bk][bn] = b4;
        __syncthreads();
#pragma unroll
        for (int k = 0; k < 16; k++) {
            float ar[4], br[4];
#pragma unroll
            for (int i = 0; i < 4; i++) ar[i] = As[k][ty * 4 + i];
            float4 bb = *(float4*)&Bs[k][tx * 4];
            br[0] = bb.x; br[1] = bb.y; br[2] = bb.z; br[3] = bb.w;
#pragma unroll
            for (int i = 0; i < 4; i++)
#pragma unroll
                for (int j = 0; j < 4; j++) acc[i][j] += ar[i] * br[j];
        }
        __syncthreads();
    }
#pragma unroll
    for (int i = 0; i < 4; i++) {
        int r = row0 + ty * 4 + i;
#pragma unroll
        for (int j = 0; j < 4; j++) {
            int c = col0 + tx * 4 + j;
            float v = acc[i][j] + bias[c];
            if (res) v += res[(size_t)r * N + c];
            if (relu) v = fmaxf(v, 0.f);
            C[(size_t)r * N + c] = v;
        }
    }
}

// ---------------- batched QK^T: S[z,m,n] = scale * sum_d Q[b,m,h*64+d]*K[b,n,h*64+d] ----------------
__global__ void qk_kernel(const float* __restrict__ Q, const float* __restrict__ Kc,
                          float* __restrict__ Sc, int Lq, int Lk, float scale) {
    int z = blockIdx.z, b = z / NHEAD, h = z % NHEAD;
    const float* Qb = Q + (size_t)b * Lq * D_MODEL + h * DK;
    const float* Kb = Kc + (size_t)b * Lk * D_MODEL + h * DK;
    float* Sb = Sc + (size_t)z * Lq * Lk;
    __shared__ float Qs[16][64];
    __shared__ float Ks[16][64];
    int m0 = blockIdx.y * 64, n0 = blockIdx.x * 64;
    int tid = threadIdx.x;
    int tx = tid & 15, ty = tid >> 4;
    int am = tid >> 2, ak = (tid & 3) * 4;
    float acc[4][4] = {};
    for (int k0 = 0; k0 < DK; k0 += 16) {
        float4 a4 = *(const float4*)(Qb + (size_t)(m0 + am) * D_MODEL + k0 + ak);
        float4 b4 = *(const float4*)(Kb + (size_t)(n0 + am) * D_MODEL + k0 + ak);
        Qs[ak + 0][am] = a4.x; Qs[ak + 1][am] = a4.y;
        Qs[ak + 2][am] = a4.z; Qs[ak + 3][am] = a4.w;
        Ks[ak + 0][am] = b4.x; Ks[ak + 1][am] = b4.y;
        Ks[ak + 2][am] = b4.z; Ks[ak + 3][am] = b4.w;
        __syncthreads();
#pragma unroll
        for (int k = 0; k < 16; k++) {
            float ar[4], br[4];
#pragma unroll
            for (int i = 0; i < 4; i++) { ar[i] = Qs[k][ty * 4 + i]; br[i] = Ks[k][tx * 4 + i]; }
#pragma unroll
            for (int i = 0; i < 4; i++)
#pragma unroll
                for (int j = 0; j < 4; j++) acc[i][j] += ar[i] * br[j];
        }
        __syncthreads();
    }
#pragma unroll
    for (int i = 0; i < 4; i++)
#pragma unroll
        for (int j = 0; j < 4; j++)
            Sb[(size_t)(m0 + ty * 4 + i) * Lk + n0 + tx * 4 + j] = acc[i][j] * scale;
}

// ---------------- masked softmax over last dim, in place. warp per row ----------------
template <int LK>
__global__ void softmax_kernel(float* __restrict__ Sc, const int* __restrict__ amask,
                               int Lq, int maskStride, int causal) {
    int warp = (blockIdx.x * blockDim.x + threadIdx.x) >> 5;
    int lane = threadIdx.x & 31;
    int total = BATCH * NHEAD * Lq;
    if (warp >= total) return;
    int qi = warp % Lq;
    int b  = warp / (NHEAD * Lq);
    float* row = Sc + (size_t)warp * LK;
    const int* mrow = amask + (size_t)b * maskStride;
    const int NPER = LK / 32;
    float vals[NPER];
    float mx = -1e30f;
#pragma unroll
    for (int j = 0; j < NPER; j++) {
        int ki = lane + j * 32;
        bool ok = (mrow[ki] != 0) && (!causal || ki <= qi);
        float v = ok ? row[ki] : -10000.0f;
        vals[j] = v; mx = fmaxf(mx, v);
    }
#pragma unroll
    for (int o = 16; o > 0; o >>= 1) mx = fmaxf(mx, __shfl_xor_sync(0xffffffffu, mx, o));
    float sum = 0.f;
#pragma unroll
    for (int j = 0; j < NPER; j++) { vals[j] = expf(vals[j] - mx); sum += vals[j]; }
#pragma unroll
    for (int o = 16; o > 0; o >>= 1) sum += __shfl_xor_sync(0xffffffffu, sum, o);
    float inv = 1.0f / sum;
#pragma unroll
    for (int j = 0; j < NPER; j++) row[lane + j * 32] = vals[j] * inv;
}

// ---------------- batched P@V: O[b,m,h*64+n] = sum_k P[z,m,k]*V[b,k,h*64+n] ----------------
__global__ void pv_kernel(const float* __restrict__ P, const float* __restrict__ V,
                          float* __restrict__ O, int Lq, int Lk) {
    int z = blockIdx.z, b = z / NHEAD, h = z % NHEAD;
    const float* Pb = P + (size_t)z * Lq * Lk;
    const float* Vb = V + (size_t)b * Lk * D_MODEL + h * DK;
    float*       Ob = O + (size_t)b * Lq * D_MODEL + h * DK;
    int m0 = blockIdx.y * 64;  // N tile is the full 64-wide head dim
    __shared__ float Ps[16][64];
    __shared__ float Vs[16][64];
    int tid = threadIdx.x;
    int tx = tid & 15, ty = tid >> 4;
    int am = tid >> 2, ak = (tid & 3) * 4;
    int bk = tid >> 4, bn = (tid & 15) * 4;
    float acc[4][4] = {};
    for (int k0 = 0; k0 < Lk; k0 += 16) {
        float4 a4 = *(const float4*)(Pb + (size_t)(m0 + am) * Lk + k0 + ak);
        float4 b4 = *(const float4*)(Vb + (size_t)(k0 + bk) * D_MODEL + bn);
        Ps[ak + 0][am] = a4.x; Ps[ak + 1][am] = a4.y;
        Ps[ak + 2][am] = a4.z; Ps[ak + 3][am] = a4.w;
        *(float4*)&Vs[bk][bn] = b4;
        __syncthreads();
#pragma unroll
        for (int k = 0; k < 16; k++) {
            float ar[4], br[4];
#pragma unroll
            for (int i = 0; i < 4; i++) ar[i] = Ps[k][ty * 4 + i];
            float4 bb = *(float4*)&Vs[k][tx * 4];
            br[0] = bb.x; br[1] = bb.y; br[2] = bb.z; br[3] = bb.w;
#pragma unroll
            for (int i = 0; i < 4; i++)
#pragma unroll
                for (int j = 0; j < 4; j++) acc[i][j] += ar[i] * br[j];
        }
        __syncthreads();
    }
#pragma unroll
    for (int i = 0; i < 4; i++)
#pragma unroll
        for (int j = 0; j < 4; j++)
            Ob[(size_t)(m0 + ty * 4 + i) * D_MODEL + tx * 4 + j] = acc[i][j];
}

// ---------------- final log_softmax (warp per row, 512 cols) ----------------
__global__ void logsoftmax_kernel(const float* __restrict__ X, float* __restrict__ Out) {
    int warp = (blockIdx.x * blockDim.x + threadIdx.x) >> 5;
    int lane = threadIdx.x & 31;
    if (warp >= MT) return;
    const float* r = X + (size_t)warp * VOCAB;
    float v[16], mx = -1e30f;
#pragma unroll
    for (int j = 0; j < 16; j++) { v[j] = r[lane + j * 32]; mx = fmaxf(mx, v[j]); }
#pragma unroll
    for (int o = 16; o > 0; o >>= 1) mx = fmaxf(mx, __shfl_xor_sync(0xffffffffu, mx, o));
    float sum = 0.f;
#pragma unroll
    for (int j = 0; j < 16; j++) sum += expf(v[j] - mx);
#pragma unroll
    for (int o = 16; o > 0; o >>= 1) sum += __shfl_xor_sync(0xffffffffu, sum, o);
    float lse = mx + logf(sum);
    float* out = Out + (size_t)warp * VOCAB;
#pragma unroll
    for (int j = 0; j < 16; j++) out[lane + j * 32] = v[j] - lse;
}

// ---------------- host driver ----------------
static float* sym(const void* s) {
    void* p = nullptr;
    cudaGetSymbolAddress(&p, s);
    return (float*)p;
}

extern "C" void kernel_launch(void* const* d_in, const int* in_sizes, int n_in,
                              void* d_out, int out_size) {
    const int*   ids    = (const int*)d_in[0];
    const int*   attm   = (const int*)d_in[1];
    const float* src    = (const float*)d_in[2];
    const int*   srcm   = (const int*)d_in[3];
    const float* emb    = (const float*)d_in[4];
    const float* sa_W   = (const float*)d_in[5];
    const float* sa_b   = (const float*)d_in[6];
    const float* ca_W   = (const float*)d_in[7];
    const float* ca_b   = (const float*)d_in[8];
    const float* ln_a   = (const float*)d_in[9];
    const float* ln_b   = (const float*)d_in[10];
    const float* ffn_w1 = (const float*)d_in[11];
    const float* ffn_b1 = (const float*)d_in[12];
    const float* ffn_w2 = (const float*)d_in[13];
    const float* ffn_b2 = (const float*)d_in[14];
    const float* fin_a  = (const float*)d_in[15];
    const float* fin_b  = (const float*)d_in[16];
    const float* lm_W   = (const float*)d_in[17];
    const float* lm_b   = (const float*)d_in[18];
    float* out = (float*)d_out;

    float* x   = sym(g_x);
    float* h   = sym(g_h);
    float* q   = sym(g_q);
    float* kb  = sym(g_k);
    float* vb  = sym(g_v);
    float* att = sym(g_att);
    float* sc  = sym(g_sc);
    float* ffn = sym(g_ffn);
    float* lg  = sym(g_lg);

    const float scale = 1.0f / 8.0f;  // 1/sqrt(64)

    // PE table + embedding
    pe_kernel<<<(LT * D_MODEL + 255) / 256, 256>>>();
    embed_kernel<<<(MT * D_MODEL + 255) / 256, 256>>>(ids, emb);

    dim3 gProjT(D_MODEL / 64, MT / 64);   // 8192 x 512
    dim3 gProjS(D_MODEL / 64, MS / 64);   // 4096 x 512
    dim3 gFfn1(D_FF / 64, MT / 64);
    dim3 gFfn2(D_MODEL / 64, MT / 64);

    for (int i = 0; i < NLAYER; i++) {
        const float* saW = sa_W + (size_t)i * 4 * D_MODEL * D_MODEL;
        const float* sab = sa_b + (size_t)i * 4 * D_MODEL;
        const float* caW = ca_W + (size_t)i * 4 * D_MODEL * D_MODEL;
        const float* cab = ca_b + (size_t)i * 4 * D_MODEL;
        const float* lnA = ln_a + (size_t)i * 3 * D_MODEL;
        const float* lnB = ln_b + (size_t)i * 3 * D_MODEL;

        // ---- self-attention ----
        ln_kernel<<<MT, 128>>>(x, h, lnA + 0 * D_MODEL, lnB + 0 * D_MODEL);
        gemm_kernel<<<gProjT, 256>>>(h, saW + 0 * D_MODEL * D_MODEL, sab + 0 * D_MODEL, nullptr, q,  MT, D_MODEL, D_MODEL, 0);
        gemm_kernel<<<gProjT, 256>>>(h, saW + 1 * D_MODEL * D_MODEL, sab + 1 * D_MODEL, nullptr, kb, MT, D_MODEL, D_MODEL, 0);
        gemm_kernel<<<gProjT, 256>>>(h, saW + 2 * D_MODEL * D_MODEL, sab + 2 * D_MODEL, nullptr, vb, MT, D_MODEL, D_MODEL, 0);
        qk_kernel<<<dim3(LT / 64, LT / 64, BATCH * NHEAD), 256>>>(q, kb, sc, LT, LT, scale);
        softmax_kernel<LT><<<(BATCH * NHEAD * LT) / 8, 256>>>(sc, attm, LT, LFULL, 1);
        pv_kernel<<<dim3(1, LT / 64, BATCH * NHEAD), 256>>>(sc, vb, att, LT, LT);
        gemm_kernel<<<gProjT, 256>>>(att, saW + 3 * D_MODEL * D_MODEL, sab + 3 * D_MODEL, x, x, MT, D_MODEL, D_MODEL, 0);

        // ---- cross-attention ----
        ln_kernel<<<MT, 128>>>(x, h, lnA + 1 * D_MODEL, lnB + 1 * D_MODEL);
        gemm_kernel<<<gProjT, 256>>>(h,   caW + 0 * D_MODEL * D_MODEL, cab + 0 * D_MODEL, nullptr, q,  MT, D_MODEL, D_MODEL, 0);
        gemm_kernel<<<gProjS, 256>>>(src, caW + 1 * D_MODEL * D_MODEL, cab + 1 * D_MODEL, nullptr, kb, MS, D_MODEL, D_MODEL, 0);
        gemm_kernel<<<gProjS, 256>>>(src, caW + 2 * D_MODEL * D_MODEL, cab + 2 * D_MODEL, nullptr, vb, MS, D_MODEL, D_MODEL, 0);
        qk_kernel<<<dim3(SRC_S / 64, LT / 64, BATCH * NHEAD), 256>>>(q, kb, sc, LT, SRC_S, scale);
        softmax_kernel<SRC_S><<<(BATCH * NHEAD * LT) / 8, 256>>>(sc, srcm, LT, SRC_S, 0);
        pv_kernel<<<dim3(1, LT / 64, BATCH * NHEAD), 256>>>(sc, vb, att, LT, SRC_S);
        gemm_kernel<<<gProjT, 256>>>(att, caW + 3 * D_MODEL * D_MODEL, cab + 3 * D_MODEL, x, x, MT, D_MODEL, D_MODEL, 0);

        // ---- FFN ----
        ln_kernel<<<MT, 128>>>(x, h, lnA + 2 * D_MODEL, lnB + 2 * D_MODEL);
        gemm_kernel<<<gFfn1, 256>>>(h, ffn_w1 + (size_t)i * D_MODEL * D_FF, ffn_b1 + (size_t)i * D_FF, nullptr, ffn, MT, D_FF, D_MODEL, 1);
        gemm_kernel<<<gFfn2, 256>>>(ffn, ffn_w2 + (size_t)i * D_FF * D_MODEL, ffn_b2 + (size_t)i * D_MODEL, x, x, MT, D_MODEL, D_FF, 0);
    }

    // final LN + LM head + log_softmax
    ln_kernel<<<MT, 128>>>(x, h, fin_a, fin_b);
    gemm_kernel<<<dim3(VOCAB / 64, MT / 64), 256>>>(h, lm_W, lm_b, nullptr, lg, MT, VOCAB, D_MODEL, 0);
    logsoftmax_kernel<<<(MT * 32 + 255) / 256, 256>>>(lg, out);
}